// round 4
// baseline (speedup 1.0000x reference)
#include <cuda_runtime.h>
#include <math_constants.h>

// Grayscale morphological erosion, 5x5 SE, 'same' padding, +inf OOB.
// image: (32,3,1024,1024) fp32 -> 96 planes of 1024x1024.
//
// Round 4: packed f32x2 subtractions.
//  - R3 geometry: 128x64 tile, block (32,8), thread = 4 contiguous cols x 8 rows.
//  - Subs via add.rn.f32x2 (2 taps/instr); mins stay scalar FMNMX.
//  - Window loaded from smem as b64/v2.b64 so pairs are register-aligned;
//    scalar halves come free via mov.b64 unpack.
//  - SE rows processed in groups {0,1,2} and {3,4} to cap constant regs.

#define TILE_W 128
#define TILE_H 64
#define RPT 8
#define SW 136            // window origin x0-4, 544B rows (16B multiple)
#define SH 68
#define F4_ROW 34
#define FILL_TOTAL (SH * F4_ROW)   // 2312
#define FILL_IT 10

typedef unsigned long long u64;

__device__ __forceinline__ u64 add2(u64 a, u64 b) {
    u64 d;
    asm("add.rn.f32x2 %0, %1, %2;" : "=l"(d) : "l"(a), "l"(b));
    return d;
}
__device__ __forceinline__ float2 unpk(u64 v) {
    float2 r;
    asm("mov.b64 {%0, %1}, %2;" : "=f"(r.x), "=f"(r.y) : "l"(v));
    return r;
}
__device__ __forceinline__ u64 pk(float lo, float hi) {
    u64 v;
    asm("mov.b64 %0, {%1, %2};" : "=l"(v) : "f"(lo), "f"(hi));
    return v;
}

// Process SE rows I0..I0+NI-1 against this thread's 4x8 output patch.
template<int I0, int NI>
__device__ __forceinline__ void process_group(const float (&s)[SH][SW],
                                              const float* __restrict__ filt,
                                              int rbase, int cbase,
                                              float (&acc)[RPT][4])
{
    // Negated packed filter constants for this group's SE rows.
    u64 P0[NI], P1[NI], Q0[NI], Q1[NI];   // (f0,f1) (f2,f3) (f1,f2) (f3,f4), negated
    float n0[NI], n4[NI];                 // -f0, -f4
#pragma unroll
    for (int k = 0; k < NI; ++k) {
        const int i = I0 + k;
        const float f0 = -__ldg(&filt[i * 5 + 0]);
        const float f1 = -__ldg(&filt[i * 5 + 1]);
        const float f2 = -__ldg(&filt[i * 5 + 2]);
        const float f3 = -__ldg(&filt[i * 5 + 3]);
        const float f4 = -__ldg(&filt[i * 5 + 4]);
        P0[k] = pk(f0, f1);
        P1[k] = pk(f2, f3);
        Q0[k] = pk(f1, f2);
        Q1[k] = pk(f3, f4);
        n0[k] = f0;
        n4[k] = f4;
    }

    // Rows needed by this group: rr = yy + i, yy in [0,RPT), i in [I0, I0+NI)
#pragma unroll
    for (int rr = I0; rr <= I0 + NI - 1 + RPT - 1; ++rr) {
        const float* row = &s[rbase + rr][cbase];
        // w[k] = smem col cbase+2+k, k=0..7. Pairs born 64-bit aligned.
        const u64 w01 = *reinterpret_cast<const u64*>(row + 2);        // 8B aligned
        const ulonglong2 w2345 = *reinterpret_cast<const ulonglong2*>(row + 4); // 16B
        const u64 w23 = w2345.x, w45 = w2345.y;
        const u64 w67 = *reinterpret_cast<const u64*>(row + 8);
        const float2 a01 = unpk(w01);
        const float2 a23 = unpk(w23);
        const float2 a45 = unpk(w45);
        const float2 a67 = unpk(w67);

#pragma unroll
        for (int k = 0; k < NI; ++k) {
            const int yy = rr - (I0 + k);
            if (yy >= 0 && yy < RPT) {
                // c = 0: (w0-f0,w1-f1) (w2-f2,w3-f3) w4-f4
                {
                    const float2 p = unpk(add2(w01, P0[k]));
                    const float2 q = unpk(add2(w23, P1[k]));
                    const float r = a45.x + n4[k];
                    acc[yy][0] = fminf(acc[yy][0],
                        fminf(fminf(fminf(p.x, p.y), fminf(q.x, q.y)), r));
                }
                // c = 1: w1-f0 (w2-f1,w3-f2) (w4-f3,w5-f4)
                {
                    const float r = a01.y + n0[k];
                    const float2 p = unpk(add2(w23, Q0[k]));
                    const float2 q = unpk(add2(w45, Q1[k]));
                    acc[yy][1] = fminf(acc[yy][1],
                        fminf(fminf(fminf(p.x, p.y), fminf(q.x, q.y)), r));
                }
                // c = 2: (w2-f0,w3-f1) (w4-f2,w5-f3) w6-f4
                {
                    const float2 p = unpk(add2(w23, P0[k]));
                    const float2 q = unpk(add2(w45, P1[k]));
                    const float r = a67.x + n4[k];
                    acc[yy][2] = fminf(acc[yy][2],
                        fminf(fminf(fminf(p.x, p.y), fminf(q.x, q.y)), r));
                }
                // c = 3: w3-f0 (w4-f1,w5-f2) (w6-f3,w7-f4)
                {
                    const float r = a23.y + n0[k];
                    const float2 p = unpk(add2(w45, Q0[k]));
                    const float2 q = unpk(add2(w67, Q1[k]));
                    acc[yy][3] = fminf(acc[yy][3],
                        fminf(fminf(fminf(p.x, p.y), fminf(q.x, q.y)), r));
                }
            }
        }
    }
}

__global__ void erosion5x5_kernel(const float* __restrict__ img,
                                  const float* __restrict__ filt,
                                  float* __restrict__ out)
{
    __shared__ float s[SH][SW];    // 36992 B

    const int tx = threadIdx.x;
    const int ty = threadIdx.y;
    const int tid = ty * 32 + tx;
    const int plane = blockIdx.z;
    const int x0 = blockIdx.x * TILE_W;
    const int y0 = blockIdx.y * TILE_H;

    const float* __restrict__ base = img + (size_t)plane * (1024 * 1024);

    // ---- Fill: front-batched predicated LDG.128, then STS.128 ----
    float4 v[FILL_IT];
    int soff[FILL_IT];
#pragma unroll
    for (int it = 0; it < FILL_IT; ++it) {
        const int idx = tid + it * 256;
        const int sy = idx / F4_ROW;
        const int k  = idx - sy * F4_ROW;
        const int gy = y0 + sy - 2;
        const int gx = x0 + 4 * k - 4;
        const bool ok = (idx < FILL_TOTAL) &&
                        ((unsigned)gy < 1024u) && ((unsigned)gx <= 1020u);
        float4 t = make_float4(CUDART_INF_F, CUDART_INF_F,
                               CUDART_INF_F, CUDART_INF_F);
        if (ok)
            t = __ldg(reinterpret_cast<const float4*>(base + (size_t)gy * 1024 + gx));
        v[it] = t;
        soff[it] = sy * SW + 4 * k;
    }
#pragma unroll
    for (int it = 0; it < FILL_IT; ++it) {
        if (it < FILL_IT - 1 || tid + it * 256 < FILL_TOTAL)
            *reinterpret_cast<float4*>(&s[0][0] + soff[it]) = v[it];
    }
    __syncthreads();

    float acc[RPT][4];
#pragma unroll
    for (int yy = 0; yy < RPT; ++yy)
#pragma unroll
        for (int c = 0; c < 4; ++c)
            acc[yy][c] = CUDART_INF_F;

    const int rbase = ty * RPT;    // first output row (tile-local)
    const int cbase = tx * 4;      // first output col (tile-local)

    process_group<0, 3>(s, filt, rbase, cbase, acc);
    process_group<3, 2>(s, filt, rbase, cbase, acc);

    // ---- Vectorized coalesced stores ----
    float* __restrict__ obase = out + (size_t)plane * (1024 * 1024);
#pragma unroll
    for (int yy = 0; yy < RPT; ++yy) {
        const int gy = y0 + rbase + yy;
        float4 st;
        st.x = acc[yy][0];
        st.y = acc[yy][1];
        st.z = acc[yy][2];
        st.w = acc[yy][3];
        *reinterpret_cast<float4*>(&obase[(size_t)gy * 1024 + x0 + cbase]) = st;
    }
}

extern "C" void kernel_launch(void* const* d_in, const int* in_sizes, int n_in,
                              void* d_out, int out_size)
{
    const float* img  = (const float*)d_in[0];   // (32,3,1024,1024) fp32
    const float* filt = (const float*)d_in[1];   // (5,5) fp32
    float* out = (float*)d_out;

    dim3 block(32, 8, 1);
    dim3 grid(1024 / TILE_W, 1024 / TILE_H, 32 * 3);
    erosion5x5_kernel<<<grid, block>>>(img, filt, out);
}

// round 5
// speedup vs baseline: 1.1012x; 1.1012x over previous
#include <cuda_runtime.h>
#include <math_constants.h>

// Grayscale morphological erosion, 5x5 SE, 'same' padding, +inf OOB.
// image: (32,3,1024,1024) fp32 -> 96 planes of 1024x1024.
//
// Round 5: packed f32x2 subs with SHARED filter pairs.
//  - R3 geometry: 128x64 tile, block (32,8), thread = 4 contiguous cols x 8 rows.
//  - Window packed into shifted pairs (3 MOV-packs/row, shared by all SE rows);
//    filter pairs P0=(-f0,-f1), P1=(-f2,-f3), n4=-f4 -> 25 const regs (same as R3).
//  - Single pass over 12 streamed rows. Math: 8 add2 + 4 FADD + 20 FMNMX
//    per (row, SE-row) for 4 columns (vs 20 FADD + 20 FMNMX scalar).

#define TILE_W 128
#define TILE_H 64
#define RPT 8
#define SW 136            // window origin x0-4, 544B rows (16B multiple)
#define SH 68
#define F4_ROW 34
#define FILL_TOTAL (SH * F4_ROW)   // 2312
#define FILL_IT 10

typedef unsigned long long u64;

__device__ __forceinline__ u64 add2(u64 a, u64 b) {
    u64 d;
    asm("add.rn.f32x2 %0, %1, %2;" : "=l"(d) : "l"(a), "l"(b));
    return d;
}
__device__ __forceinline__ float2 unpk(u64 v) {
    float2 r;
    asm("mov.b64 {%0, %1}, %2;" : "=f"(r.x), "=f"(r.y) : "l"(v));
    return r;
}
__device__ __forceinline__ u64 pk(float lo, float hi) {
    u64 v;
    asm("mov.b64 %0, {%1, %2};" : "=l"(v) : "f"(lo), "f"(hi));
    return v;
}

__global__ __launch_bounds__(256, 3)
void erosion5x5_kernel(const float* __restrict__ img,
                       const float* __restrict__ filt,
                       float* __restrict__ out)
{
    __shared__ float s[SH][SW];    // 36992 B

    const int tx = threadIdx.x;
    const int ty = threadIdx.y;
    const int tid = ty * 32 + tx;
    const int plane = blockIdx.z;
    const int x0 = blockIdx.x * TILE_W;
    const int y0 = blockIdx.y * TILE_H;

    const float* __restrict__ base = img + (size_t)plane * (1024 * 1024);

    // ---- Fill: front-batched predicated LDG.128, then STS.128 (R3) ----
    float4 v[FILL_IT];
    int soff[FILL_IT];
#pragma unroll
    for (int it = 0; it < FILL_IT; ++it) {
        const int idx = tid + it * 256;
        const int sy = idx / F4_ROW;
        const int k  = idx - sy * F4_ROW;
        const int gy = y0 + sy - 2;
        const int gx = x0 + 4 * k - 4;
        const bool ok = (idx < FILL_TOTAL) &&
                        ((unsigned)gy < 1024u) && ((unsigned)gx <= 1020u);
        float4 t = make_float4(CUDART_INF_F, CUDART_INF_F,
                               CUDART_INF_F, CUDART_INF_F);
        if (ok)
            t = __ldg(reinterpret_cast<const float4*>(base + (size_t)gy * 1024 + gx));
        v[it] = t;
        soff[it] = sy * SW + 4 * k;
    }
#pragma unroll
    for (int it = 0; it < FILL_IT; ++it) {
        if (it < FILL_IT - 1 || tid + it * 256 < FILL_TOTAL)
            *reinterpret_cast<float4*>(&s[0][0] + soff[it]) = v[it];
    }
    __syncthreads();

    // ---- Negated packed filter constants: 5 regs per SE row (25 total) ----
    u64 P0[5], P1[5];
    float n4[5];
#pragma unroll
    for (int i = 0; i < 5; ++i) {
        const float f0 = -__ldg(&filt[i * 5 + 0]);
        const float f1 = -__ldg(&filt[i * 5 + 1]);
        const float f2 = -__ldg(&filt[i * 5 + 2]);
        const float f3 = -__ldg(&filt[i * 5 + 3]);
        P0[i] = pk(f0, f1);
        P1[i] = pk(f2, f3);
        n4[i] = -__ldg(&filt[i * 5 + 4]);
    }

    float acc[RPT][4];
#pragma unroll
    for (int yy = 0; yy < RPT; ++yy)
#pragma unroll
        for (int c = 0; c < 4; ++c)
            acc[yy][c] = CUDART_INF_F;

    const int rbase = ty * RPT;    // first output row (tile-local)
    const int cbase = tx * 4;      // first output col (tile-local)

    // ---- Stream 12 input rows feeding this thread's 8 output rows ----
#pragma unroll
    for (int rr = 0; rr < RPT + 4; ++rr) {
        const float* row = &s[rbase + rr][cbase];
        // w[k] = smem col cbase+2+k, k=0..7; even pairs born 64-bit aligned.
        const u64 w01 = *reinterpret_cast<const u64*>(row + 2);        // 8B
        const ulonglong2 w2345 = *reinterpret_cast<const ulonglong2*>(row + 4); // 16B
        const u64 w23 = w2345.x, w45 = w2345.y;
        const u64 w67 = *reinterpret_cast<const u64*>(row + 8);
        const float2 a01 = unpk(w01);
        const float2 a23 = unpk(w23);
        const float2 a45 = unpk(w45);
        const float2 a67 = unpk(w67);
        // Odd shifted pairs, shared across all SE rows this iteration.
        const u64 o12 = pk(a01.y, a23.x);
        const u64 o34 = pk(a23.y, a45.x);
        const u64 o56 = pk(a45.y, a67.x);

#pragma unroll
        for (int i = 0; i < 5; ++i) {
            const int yy = rr - i;        // output row fed by SE row i
            if (yy >= 0 && yy < RPT) {
                // c = 0
                {
                    const float2 p = unpk(add2(w01, P0[i]));
                    const float2 q = unpk(add2(w23, P1[i]));
                    const float r = a45.x + n4[i];
                    acc[yy][0] = fminf(acc[yy][0],
                        fminf(fminf(fminf(p.x, p.y), fminf(q.x, q.y)), r));
                }
                // c = 1
                {
                    const float2 p = unpk(add2(o12, P0[i]));
                    const float2 q = unpk(add2(o34, P1[i]));
                    const float r = a45.y + n4[i];
                    acc[yy][1] = fminf(acc[yy][1],
                        fminf(fminf(fminf(p.x, p.y), fminf(q.x, q.y)), r));
                }
                // c = 2
                {
                    const float2 p = unpk(add2(w23, P0[i]));
                    const float2 q = unpk(add2(w45, P1[i]));
                    const float r = a67.x + n4[i];
                    acc[yy][2] = fminf(acc[yy][2],
                        fminf(fminf(fminf(p.x, p.y), fminf(q.x, q.y)), r));
                }
                // c = 3
                {
                    const float2 p = unpk(add2(o34, P0[i]));
                    const float2 q = unpk(add2(o56, P1[i]));
                    const float r = a67.y + n4[i];
                    acc[yy][3] = fminf(acc[yy][3],
                        fminf(fminf(fminf(p.x, p.y), fminf(q.x, q.y)), r));
                }
            }
        }
    }

    // ---- Vectorized coalesced stores ----
    float* __restrict__ obase = out + (size_t)plane * (1024 * 1024);
#pragma unroll
    for (int yy = 0; yy < RPT; ++yy) {
        const int gy = y0 + rbase + yy;
        float4 st;
        st.x = acc[yy][0];
        st.y = acc[yy][1];
        st.z = acc[yy][2];
        st.w = acc[yy][3];
        *reinterpret_cast<float4*>(&obase[(size_t)gy * 1024 + x0 + cbase]) = st;
    }
}

extern "C" void kernel_launch(void* const* d_in, const int* in_sizes, int n_in,
                              void* d_out, int out_size)
{
    const float* img  = (const float*)d_in[0];   // (32,3,1024,1024) fp32
    const float* filt = (const float*)d_in[1];   // (5,5) fp32
    float* out = (float*)d_out;

    dim3 block(32, 8, 1);
    dim3 grid(1024 / TILE_W, 1024 / TILE_H, 32 * 3);
    erosion5x5_kernel<<<grid, block>>>(img, filt, out);
}